// round 4
// baseline (speedup 1.0000x reference)
#include <cuda_runtime.h>
#include <math.h>

// ---------------------------------------------------------------------------
// CLFormer v3 for GB300 (sm_103a).  B=32, C=32, L=16384, H=4(dh=8), NB=3.
// v3 vs v2: j-split FCs (lower reg liveness) + __launch_bounds__(128,5),
// NCH=64 chunks (grid 2048 -> small wave tail), 3-term A&S erf GELU.
// ---------------------------------------------------------------------------

#define Bn 32
#define Cn 32
#define Ln 16384
#define NCH 64          // chunks per batch row
#define CHT 256         // tokens per chunk
#define NTH 128
#define NGR 2           // groups of 128 tokens per chunk
#define HST 36          // smem h stride (floats), conflict-free & 16B-aligned

typedef unsigned long long u64;

__device__ float g_h[(size_t)Bn * Cn * Ln];     // 64MB activations (in place)
__device__ float g_partA[Bn * NCH * 288];       // per (b,ch): S[32] | M[256]
__device__ float g_partB[Bn * NCH * 288];
__device__ float g_pool[Bn * NCH * 32];

// ---- packed f32x2 helpers --------------------------------------------------
__device__ __forceinline__ u64 dup2(float a) {
    u64 r; asm("mov.b64 %0, {%1, %1};" : "=l"(r) : "f"(a)); return r;
}
__device__ __forceinline__ void fma2(u64& d, u64 a, u64 b) {
    asm("fma.rn.f32x2 %0, %1, %2, %0;" : "+l"(d) : "l"(a), "l"(b));
}
__device__ __forceinline__ float2 unpk(u64 v) {
    float2 f; asm("mov.b64 {%0, %1}, %2;" : "=f"(f.x), "=f"(f.y) : "l"(v)); return f;
}
__device__ __forceinline__ float frcp(float x) {
    float r; asm("rcp.approx.f32 %0, %1;" : "=f"(r) : "f"(x)); return r;
}

// GELU with A&S 7.1.25 3-term erf (max abs err 2.5e-5), branch-free
__device__ __forceinline__ float gelu_f(float x) {
    float z = fabsf(x) * 0.7071067811865476f;
    float t = frcp(fmaf(0.47047f, z, 1.0f));
    float p = t * fmaf(t, fmaf(t, 0.7478556f, -0.0958798f), 0.3480242f);
    float er = copysignf(fmaf(-p, __expf(-z * z), 1.0f), x);
    return 0.5f * x * (1.0f + er);
}

// ---- stats helpers ----------------------------------------------------------
__device__ __forceinline__ void stage_h(float* hS, int tid, const float (&h)[32]) {
    float4* d = reinterpret_cast<float4*>(hS + tid * HST);
#pragma unroll
    for (int k = 0; k < 8; k++)
        d[k] = make_float4(h[4 * k], h[4 * k + 1], h[4 * k + 2], h[4 * k + 3]);
}

// thread owns M row r (head=r>>3, d=r&7) over token-quarter q
__device__ __forceinline__ void accum_stats(const float* hS, int r, int q,
        u64& m0, u64& m1, u64& m2, u64& m3, float& sacc) {
    const float* p = hS + q * 32 * HST;
    const int eoff = (r & 24);  // head*8
#pragma unroll 4
    for (int s = 0; s < 32; s++) {
        float ed = __expf(p[r]);
        ulonglong2 hv = *reinterpret_cast<const ulonglong2*>(p + eoff);
        ulonglong2 hw = *reinterpret_cast<const ulonglong2*>(p + eoff + 4);
        u64 e2 = dup2(ed);
        fma2(m0, e2, hv.x); fma2(m1, e2, hv.y);
        fma2(m2, e2, hw.x); fma2(m3, e2, hw.y);
        sacc += ed;
        p += HST;
    }
}

// reduce 4 quarters via smem (red aliases hS), write chunk partial to gout
__device__ __forceinline__ void writeout_stats(float* red, float* gout, int tid,
        u64 m0, u64 m1, u64 m2, u64 m3, float sacc) {
    int r = tid & 31, q = tid >> 5;
    float2 a = unpk(m0), b = unpk(m1), c = unpk(m2), d = unpk(m3);
    float4* dst = reinterpret_cast<float4*>(red + q * 288 + r * 8);
    dst[0] = make_float4(a.x, a.y, b.x, b.y);
    dst[1] = make_float4(c.x, c.y, d.x, d.y);
    red[q * 288 + 256 + r] = sacc;
    __syncthreads();
    float M0 = red[tid] + red[288 + tid] + red[576 + tid] + red[864 + tid];
    float M1 = red[128 + tid] + red[416 + tid] + red[704 + tid] + red[992 + tid];
    gout[32 + tid] = M0;
    gout[160 + tid] = M1;
    if (tid < 32)
        gout[tid] = red[256 + tid] + red[544 + tid] + red[832 + tid] + red[1120 + tid];
}

// ---------------------------------------------------------------------------
// Kernel 1: stats over raw x -> g_partA
// ---------------------------------------------------------------------------
__global__ __launch_bounds__(NTH, 5) void stats_x_kernel(const float* __restrict__ x) {
    __shared__ __align__(16) float hS[NTH * HST];
    int tid = threadIdx.x, b = blockIdx.y, ch = blockIdx.x;
    int r = tid & 31, q = tid >> 5;
    const float* xb = x + (size_t)b * Cn * Ln + ch * CHT;
    u64 m0 = 0, m1 = 0, m2 = 0, m3 = 0; float sacc = 0.f;
    for (int g = 0; g < NGR; g++) {
        int l = g * NTH + tid;
        float h[32];
#pragma unroll
        for (int c = 0; c < 32; c++) h[c] = xb[(size_t)c * Ln + l];
        stage_h(hS, tid, h);
        __syncthreads();
        accum_stats(hS, r, q, m0, m1, m2, m3, sacc);
        __syncthreads();
    }
    writeout_stats(hS, g_partA + (size_t)(b * NCH + ch) * 288, tid, m0, m1, m2, m3, sacc);
}

// ---------------------------------------------------------------------------
// Kernel 2: token pass. Prologue folds the partial-combine (kv). Body: attn,
// FC1+GELU, FC2+GELU (both FCs in two j-halves to cap register liveness),
// then next-block stats (or pool partials for LAST).
// ---------------------------------------------------------------------------
template <bool FROM_X, bool LAST, int IN_A>
__global__ __launch_bounds__(NTH, 5) void token_kernel(
        const float* __restrict__ xin,
        const float* __restrict__ W1, const float* __restrict__ b1,
        const float* __restrict__ W2, const float* __restrict__ b2) {
    __shared__ __align__(16) float hS[NTH * HST];
    __shared__ __align__(16) float sW1[1024], sW2[1024], skv[256], sS[32], sb1[32], sb2[32];
    int tid = threadIdx.x, b = blockIdx.y, ch = blockIdx.x;
    int r = tid & 31, q = tid >> 5;

    const float* pin = IN_A ? g_partA : g_partB;
    float* pout = IN_A ? g_partB : g_partA;

    // prologue: combine chunk partials -> kv; load weights
    const float* pp = pin + (size_t)b * NCH * 288;
    float m0p = 0.f, m1p = 0.f;
#pragma unroll 4
    for (int c2 = 0; c2 < NCH; c2++) {
        m0p += pp[c2 * 288 + 32 + tid];
        m1p += pp[c2 * 288 + 160 + tid];
    }
    if (tid < 32) {
        float s = 0.f;
#pragma unroll 4
        for (int c2 = 0; c2 < NCH; c2++) s += pp[c2 * 288 + tid];
        sS[tid] = s;
        sb1[tid] = b1[tid];
        sb2[tid] = b2[tid];
    }
    for (int i = tid; i < 1024; i += NTH) { sW1[i] = W1[i]; sW2[i] = W2[i]; }
    __syncthreads();
    {
        int u0 = tid, u1 = tid + 128;
        int cd0 = ((u0 >> 6) << 3) | ((u0 >> 3) & 7);
        int cd1 = ((u1 >> 6) << 3) | ((u1 >> 3) & 7);
        skv[u0] = m0p / sS[cd0];
        skv[u1] = m1p / sS[cd1];
    }
    __syncthreads();

    u64 m0 = 0, m1 = 0, m2 = 0, m3 = 0; float sacc = 0.f, pacc = 0.f;
    const float* inb = FROM_X ? (xin + (size_t)b * Cn * Ln + ch * CHT)
                              : (g_h + (size_t)b * Cn * Ln + ch * CHT);
    float* outb = g_h + (size_t)b * Cn * Ln + ch * CHT;

    for (int g = 0; g < NGR; g++) {
        int l = g * NTH + tid;
        float h[32];
#pragma unroll
        for (int c = 0; c < 32; c++) h[c] = inb[(size_t)c * Ln + l];

        // ---- attention: q-softmax over dh (no max; bounded), @ kv ----
#pragma unroll
        for (int hd = 0; hd < 4; hd++) {
            float es[8]; float sum = 0.f;
#pragma unroll
            for (int d = 0; d < 8; d++) { es[d] = __expf(h[hd * 8 + d]); sum += es[d]; }
            u64 a0 = 0, a1 = 0, a2 = 0, a3 = 0;
#pragma unroll
            for (int d = 0; d < 8; d++) {
                const ulonglong2* kr = reinterpret_cast<const ulonglong2*>(&skv[hd * 64 + d * 8]);
                ulonglong2 k0 = kr[0], k1 = kr[1];
                u64 e2 = dup2(es[d]);
                fma2(a0, e2, k0.x); fma2(a1, e2, k0.y);
                fma2(a2, e2, k1.x); fma2(a3, e2, k1.y);
            }
            float inv = frcp(sum);
            float2 u;
            u = unpk(a0); h[hd * 8 + 0] = u.x * inv; h[hd * 8 + 1] = u.y * inv;
            u = unpk(a1); h[hd * 8 + 2] = u.x * inv; h[hd * 8 + 3] = u.y * inv;
            u = unpk(a2); h[hd * 8 + 4] = u.x * inv; h[hd * 8 + 5] = u.y * inv;
            u = unpk(a3); h[hd * 8 + 6] = u.x * inv; h[hd * 8 + 7] = u.y * inv;
        }

        // ---- FC1 + GELU (two j-halves of 16 outputs each) ----
        float f[32];
#pragma unroll
        for (int half = 0; half < 2; half++) {
            const int jb = half * 16;
            u64 acc[8];
            {
                const ulonglong2* bb = reinterpret_cast<const ulonglong2*>(sb1 + jb);
#pragma unroll
                for (int k = 0; k < 4; k++) { ulonglong2 v = bb[k]; acc[2 * k] = v.x; acc[2 * k + 1] = v.y; }
            }
#pragma unroll
            for (int i = 0; i < 32; i++) {
                u64 ai = dup2(h[i]);
                const ulonglong2* wr = reinterpret_cast<const ulonglong2*>(&sW1[i * 32 + jb]);
#pragma unroll
                for (int k = 0; k < 4; k++) {
                    ulonglong2 w = wr[k];
                    fma2(acc[2 * k], ai, w.x);
                    fma2(acc[2 * k + 1], ai, w.y);
                }
            }
#pragma unroll
            for (int k = 0; k < 8; k++) {
                float2 u = unpk(acc[k]);
                f[jb + 2 * k] = gelu_f(u.x);
                f[jb + 2 * k + 1] = gelu_f(u.y);
            }
        }

        // ---- FC2 + GELU (two j-halves) ----
#pragma unroll
        for (int half = 0; half < 2; half++) {
            const int jb = half * 16;
            u64 acc[8];
            {
                const ulonglong2* bb = reinterpret_cast<const ulonglong2*>(sb2 + jb);
#pragma unroll
                for (int k = 0; k < 4; k++) { ulonglong2 v = bb[k]; acc[2 * k] = v.x; acc[2 * k + 1] = v.y; }
            }
#pragma unroll
            for (int i = 0; i < 32; i++) {
                u64 ai = dup2(f[i]);
                const ulonglong2* wr = reinterpret_cast<const ulonglong2*>(&sW2[i * 32 + jb]);
#pragma unroll
                for (int k = 0; k < 4; k++) {
                    ulonglong2 w = wr[k];
                    fma2(acc[2 * k], ai, w.x);
                    fma2(acc[2 * k + 1], ai, w.y);
                }
            }
#pragma unroll
            for (int k = 0; k < 8; k++) {
                float2 u = unpk(acc[k]);
                h[jb + 2 * k] = gelu_f(u.x);
                h[jb + 2 * k + 1] = gelu_f(u.y);
            }
        }

        if (!LAST) {
#pragma unroll
            for (int c = 0; c < 32; c++) outb[(size_t)c * Ln + l] = h[c];
        }
        stage_h(hS, tid, h);
        __syncthreads();
        if (!LAST) {
            accum_stats(hS, r, q, m0, m1, m2, m3, sacc);
        } else {
            const float* p = hS + q * 32 * HST;
#pragma unroll 8
            for (int s = 0; s < 32; s++) { pacc += p[r]; p += HST; }
        }
        __syncthreads();
    }

    if (!LAST) {
        writeout_stats(hS, pout + (size_t)(b * NCH + ch) * 288, tid, m0, m1, m2, m3, sacc);
    } else {
        hS[q * 32 + r] = pacc;
        __syncthreads();
        if (tid < 32)
            g_pool[(size_t)(b * NCH + ch) * 32 + tid] =
                hS[tid] + hS[32 + tid] + hS[64 + tid] + hS[96 + tid];
    }
}

// ---------------------------------------------------------------------------
// Kernel 3: head (pool-finish, Linear, BN(eval), GELU, Linear)
// ---------------------------------------------------------------------------
__global__ __launch_bounds__(32) void final_kernel(
        const float* __restrict__ Wh, const float* __restrict__ bh,
        const float* __restrict__ gamma, const float* __restrict__ beta,
        const float* __restrict__ mu, const float* __restrict__ var,
        const float* __restrict__ Wf, const float* __restrict__ bf,
        float* __restrict__ out) {
    int b = threadIdx.x;
    if (b >= Bn) return;
    float p[32];
#pragma unroll
    for (int c = 0; c < 32; c++) {
        float sum = 0.f;
        for (int ch = 0; ch < NCH; ch++)
            sum += g_pool[(size_t)(b * NCH + ch) * 32 + c];
        p[c] = sum * (1.0f / (float)Ln);
    }
    float z[32];
#pragma unroll
    for (int j = 0; j < 32; j++) {
        float sv = bh[j];
#pragma unroll
        for (int c = 0; c < 32; c++) sv += p[c] * Wh[c * 32 + j];
        sv = (sv - mu[j]) * rsqrtf(var[j] + 1e-5f) * gamma[j] + beta[j];
        z[j] = 0.5f * sv * (1.0f + erff(sv * 0.7071067811865476f));
    }
    for (int k = 0; k < 10; k++) {
        float sv = bf[k];
#pragma unroll
        for (int j = 0; j < 32; j++) sv += z[j] * Wf[j * 10 + k];
        out[b * 10 + k] = sv;
    }
}

// ---------------------------------------------------------------------------
extern "C" void kernel_launch(void* const* d_in, const int* in_sizes, int n_in,
                              void* d_out, int out_size) {
    const float* x    = (const float*)d_in[0];
    const float* fcW1 = (const float*)d_in[1];
    const float* fcb1 = (const float*)d_in[2];
    const float* fcW2 = (const float*)d_in[3];
    const float* fcb2 = (const float*)d_in[4];
    const float* Wh   = (const float*)d_in[5];
    const float* bh   = (const float*)d_in[6];
    const float* gam  = (const float*)d_in[7];
    const float* bet  = (const float*)d_in[8];
    const float* mu   = (const float*)d_in[9];
    const float* var  = (const float*)d_in[10];
    const float* Wf   = (const float*)d_in[11];
    const float* bf   = (const float*)d_in[12];
    float* out = (float*)d_out;

    dim3 grid(NCH, Bn);
    stats_x_kernel<<<grid, NTH>>>(x);                                  // -> partA
    token_kernel<true,  false, 1><<<grid, NTH>>>(x, fcW1, fcb1, fcW2, fcb2);          // A->B
    token_kernel<false, false, 0><<<grid, NTH>>>(nullptr, fcW1 + 1024, fcb1 + 32,
                                                 fcW2 + 1024, fcb2 + 32);             // B->A
    token_kernel<false, true,  1><<<grid, NTH>>>(nullptr, fcW1 + 2048, fcb1 + 64,
                                                 fcW2 + 2048, fcb2 + 64);             // A->pool
    final_kernel<<<1, 32>>>(Wh, bh, gam, bet, mu, var, Wf, bf, out);
}

// round 5
// speedup vs baseline: 1.1106x; 1.1106x over previous
#include <cuda_runtime.h>
#include <math.h>

// ---------------------------------------------------------------------------
// CLFormer v5 for GB300 (sm_103a).  B=32, C=32, L=16384, H=4(dh=8), NB=3.
// v5 vs v4: separate tiny combine kernel (folded combine at NCH=64 was the
// regression: ~135MB L2 re-reads per token kernel), keep NCH=64 tail fix,
// keep 96-reg j-split body + launch_bounds(128,5), 3-term A&S GELU.
// Launches: stats_x, (combine, token)x3, final = 8.
// ---------------------------------------------------------------------------

#define Bn 32
#define Cn 32
#define Ln 16384
#define NCH 64          // chunks per batch row
#define CHT 256         // tokens per chunk
#define NTH 128
#define NGR 2           // groups of 128 tokens per chunk
#define HST 36          // smem h stride (floats), conflict-free & 16B-aligned

typedef unsigned long long u64;

__device__ float g_h[(size_t)Bn * Cn * Ln];     // 64MB activations (in place)
__device__ float g_part[Bn * NCH * 288];        // per (b,ch): S[32] | M[256]
__device__ float g_kv[Bn * 256];                // combined kv per batch
__device__ float g_pool[Bn * NCH * 32];

// ---- packed f32x2 helpers --------------------------------------------------
__device__ __forceinline__ u64 dup2(float a) {
    u64 r; asm("mov.b64 %0, {%1, %1};" : "=l"(r) : "f"(a)); return r;
}
__device__ __forceinline__ void fma2(u64& d, u64 a, u64 b) {
    asm("fma.rn.f32x2 %0, %1, %2, %0;" : "+l"(d) : "l"(a), "l"(b));
}
__device__ __forceinline__ float2 unpk(u64 v) {
    float2 f; asm("mov.b64 {%0, %1}, %2;" : "=f"(f.x), "=f"(f.y) : "l"(v)); return f;
}
__device__ __forceinline__ float frcp(float x) {
    float r; asm("rcp.approx.f32 %0, %1;" : "=f"(r) : "f"(x)); return r;
}

// GELU with A&S 7.1.25 3-term erf (max abs err 2.5e-5), branch-free
__device__ __forceinline__ float gelu_f(float x) {
    float z = fabsf(x) * 0.7071067811865476f;
    float t = frcp(fmaf(0.47047f, z, 1.0f));
    float p = t * fmaf(t, fmaf(t, 0.7478556f, -0.0958798f), 0.3480242f);
    float er = copysignf(fmaf(-p, __expf(-z * z), 1.0f), x);
    return 0.5f * x * (1.0f + er);
}

// ---- stats helpers ----------------------------------------------------------
__device__ __forceinline__ void stage_h(float* hS, int tid, const float (&h)[32]) {
    float4* d = reinterpret_cast<float4*>(hS + tid * HST);
#pragma unroll
    for (int k = 0; k < 8; k++)
        d[k] = make_float4(h[4 * k], h[4 * k + 1], h[4 * k + 2], h[4 * k + 3]);
}

// thread owns M row r (head=r>>3, d=r&7) over token-quarter q
__device__ __forceinline__ void accum_stats(const float* hS, int r, int q,
        u64& m0, u64& m1, u64& m2, u64& m3, float& sacc) {
    const float* p = hS + q * 32 * HST;
    const int eoff = (r & 24);  // head*8
#pragma unroll 4
    for (int s = 0; s < 32; s++) {
        float ed = __expf(p[r]);
        ulonglong2 hv = *reinterpret_cast<const ulonglong2*>(p + eoff);
        ulonglong2 hw = *reinterpret_cast<const ulonglong2*>(p + eoff + 4);
        u64 e2 = dup2(ed);
        fma2(m0, e2, hv.x); fma2(m1, e2, hv.y);
        fma2(m2, e2, hw.x); fma2(m3, e2, hw.y);
        sacc += ed;
        p += HST;
    }
}

// reduce 4 quarters via smem (red aliases hS), write chunk partial to gout
__device__ __forceinline__ void writeout_stats(float* red, float* gout, int tid,
        u64 m0, u64 m1, u64 m2, u64 m3, float sacc) {
    int r = tid & 31, q = tid >> 5;
    float2 a = unpk(m0), b = unpk(m1), c = unpk(m2), d = unpk(m3);
    float4* dst = reinterpret_cast<float4*>(red + q * 288 + r * 8);
    dst[0] = make_float4(a.x, a.y, b.x, b.y);
    dst[1] = make_float4(c.x, c.y, d.x, d.y);
    red[q * 288 + 256 + r] = sacc;
    __syncthreads();
    float M0 = red[tid] + red[288 + tid] + red[576 + tid] + red[864 + tid];
    float M1 = red[128 + tid] + red[416 + tid] + red[704 + tid] + red[992 + tid];
    gout[32 + tid] = M0;
    gout[160 + tid] = M1;
    if (tid < 32)
        gout[tid] = red[256 + tid] + red[544 + tid] + red[832 + tid] + red[1120 + tid];
}

// ---------------------------------------------------------------------------
// Kernel 1: stats over raw x -> g_part
// ---------------------------------------------------------------------------
__global__ __launch_bounds__(NTH, 5) void stats_x_kernel(const float* __restrict__ x) {
    __shared__ __align__(16) float hS[NTH * HST];
    int tid = threadIdx.x, b = blockIdx.y, ch = blockIdx.x;
    int r = tid & 31, q = tid >> 5;
    const float* xb = x + (size_t)b * Cn * Ln + ch * CHT;
    u64 m0 = 0, m1 = 0, m2 = 0, m3 = 0; float sacc = 0.f;
    for (int g = 0; g < NGR; g++) {
        int l = g * NTH + tid;
        float h[32];
#pragma unroll
        for (int c = 0; c < 32; c++) h[c] = xb[(size_t)c * Ln + l];
        stage_h(hS, tid, h);
        __syncthreads();
        accum_stats(hS, r, q, m0, m1, m2, m3, sacc);
        __syncthreads();
    }
    writeout_stats(hS, g_part + (size_t)(b * NCH + ch) * 288, tid, m0, m1, m2, m3, sacc);
}

// ---------------------------------------------------------------------------
// Kernel 2: combine chunk partials into kv[b][256]  (tiny; grid = Bn)
// ---------------------------------------------------------------------------
__global__ __launch_bounds__(256) void combine_kernel() {
    int b = blockIdx.x, tid = threadIdx.x;
    __shared__ float sS[32];
    const float* pb = g_part + (size_t)b * NCH * 288;
    if (tid < 32) {
        float s = 0.f;
#pragma unroll 8
        for (int ch = 0; ch < NCH; ch++) s += pb[ch * 288 + tid];
        sS[tid] = s;
    }
    float m = 0.f;
#pragma unroll 8
    for (int ch = 0; ch < NCH; ch++) m += pb[ch * 288 + 32 + tid];
    __syncthreads();
    int cd = ((tid >> 6) << 3) | ((tid >> 3) & 7);
    g_kv[b * 256 + tid] = m / sS[cd];
}

// ---------------------------------------------------------------------------
// Kernel 3: token pass. Body: attn, FC1+GELU, FC2+GELU (j-halved for reg
// liveness), then next-block stats (or pool partials for LAST).
// ---------------------------------------------------------------------------
template <bool FROM_X, bool LAST>
__global__ __launch_bounds__(NTH, 5) void token_kernel(
        const float* __restrict__ xin,
        const float* __restrict__ W1, const float* __restrict__ b1,
        const float* __restrict__ W2, const float* __restrict__ b2) {
    __shared__ __align__(16) float hS[NTH * HST];
    __shared__ __align__(16) float sW1[1024], sW2[1024], skv[256], sb1[32], sb2[32];
    int tid = threadIdx.x, b = blockIdx.y, ch = blockIdx.x;
    int r = tid & 31, q = tid >> 5;

    // prologue: load kv + weights (cheap)
    skv[tid] = g_kv[b * 256 + tid];
    skv[tid + 128] = g_kv[b * 256 + tid + 128];
    if (tid < 32) { sb1[tid] = b1[tid]; sb2[tid] = b2[tid]; }
    for (int i = tid; i < 1024; i += NTH) { sW1[i] = W1[i]; sW2[i] = W2[i]; }
    __syncthreads();

    u64 m0 = 0, m1 = 0, m2 = 0, m3 = 0; float sacc = 0.f, pacc = 0.f;
    const float* inb = FROM_X ? (xin + (size_t)b * Cn * Ln + ch * CHT)
                              : (g_h + (size_t)b * Cn * Ln + ch * CHT);
    float* outb = g_h + (size_t)b * Cn * Ln + ch * CHT;

    for (int g = 0; g < NGR; g++) {
        int l = g * NTH + tid;
        float h[32];
#pragma unroll
        for (int c = 0; c < 32; c++) h[c] = inb[(size_t)c * Ln + l];

        // ---- attention: q-softmax over dh (no max; bounded), @ kv ----
#pragma unroll
        for (int hd = 0; hd < 4; hd++) {
            float es[8]; float sum = 0.f;
#pragma unroll
            for (int d = 0; d < 8; d++) { es[d] = __expf(h[hd * 8 + d]); sum += es[d]; }
            u64 a0 = 0, a1 = 0, a2 = 0, a3 = 0;
#pragma unroll
            for (int d = 0; d < 8; d++) {
                const ulonglong2* kr = reinterpret_cast<const ulonglong2*>(&skv[hd * 64 + d * 8]);
                ulonglong2 k0 = kr[0], k1 = kr[1];
                u64 e2 = dup2(es[d]);
                fma2(a0, e2, k0.x); fma2(a1, e2, k0.y);
                fma2(a2, e2, k1.x); fma2(a3, e2, k1.y);
            }
            float inv = frcp(sum);
            float2 u;
            u = unpk(a0); h[hd * 8 + 0] = u.x * inv; h[hd * 8 + 1] = u.y * inv;
            u = unpk(a1); h[hd * 8 + 2] = u.x * inv; h[hd * 8 + 3] = u.y * inv;
            u = unpk(a2); h[hd * 8 + 4] = u.x * inv; h[hd * 8 + 5] = u.y * inv;
            u = unpk(a3); h[hd * 8 + 6] = u.x * inv; h[hd * 8 + 7] = u.y * inv;
        }

        // ---- FC1 + GELU (two j-halves of 16 outputs each) ----
        float f[32];
#pragma unroll
        for (int half = 0; half < 2; half++) {
            const int jb = half * 16;
            u64 acc[8];
            {
                const ulonglong2* bb = reinterpret_cast<const ulonglong2*>(sb1 + jb);
#pragma unroll
                for (int k = 0; k < 4; k++) { ulonglong2 v = bb[k]; acc[2 * k] = v.x; acc[2 * k + 1] = v.y; }
            }
#pragma unroll
            for (int i = 0; i < 32; i++) {
                u64 ai = dup2(h[i]);
                const ulonglong2* wr = reinterpret_cast<const ulonglong2*>(&sW1[i * 32 + jb]);
#pragma unroll
                for (int k = 0; k < 4; k++) {
                    ulonglong2 w = wr[k];
                    fma2(acc[2 * k], ai, w.x);
                    fma2(acc[2 * k + 1], ai, w.y);
                }
            }
#pragma unroll
            for (int k = 0; k < 8; k++) {
                float2 u = unpk(acc[k]);
                f[jb + 2 * k] = gelu_f(u.x);
                f[jb + 2 * k + 1] = gelu_f(u.y);
            }
        }

        // ---- FC2 + GELU (two j-halves) ----
#pragma unroll
        for (int half = 0; half < 2; half++) {
            const int jb = half * 16;
            u64 acc[8];
            {
                const ulonglong2* bb = reinterpret_cast<const ulonglong2*>(sb2 + jb);
#pragma unroll
                for (int k = 0; k < 4; k++) { ulonglong2 v = bb[k]; acc[2 * k] = v.x; acc[2 * k + 1] = v.y; }
            }
#pragma unroll
            for (int i = 0; i < 32; i++) {
                u64 ai = dup2(f[i]);
                const ulonglong2* wr = reinterpret_cast<const ulonglong2*>(&sW2[i * 32 + jb]);
#pragma unroll
                for (int k = 0; k < 4; k++) {
                    ulonglong2 w = wr[k];
                    fma2(acc[2 * k], ai, w.x);
                    fma2(acc[2 * k + 1], ai, w.y);
                }
            }
#pragma unroll
            for (int k = 0; k < 8; k++) {
                float2 u = unpk(acc[k]);
                h[jb + 2 * k] = gelu_f(u.x);
                h[jb + 2 * k + 1] = gelu_f(u.y);
            }
        }

        if (!LAST) {
#pragma unroll
            for (int c = 0; c < 32; c++) outb[(size_t)c * Ln + l] = h[c];
        }
        stage_h(hS, tid, h);
        __syncthreads();
        if (!LAST) {
            accum_stats(hS, r, q, m0, m1, m2, m3, sacc);
        } else {
            const float* p = hS + q * 32 * HST;
#pragma unroll 8
            for (int s = 0; s < 32; s++) { pacc += p[r]; p += HST; }
        }
        __syncthreads();
    }

    if (!LAST) {
        writeout_stats(hS, g_part + (size_t)(b * NCH + ch) * 288, tid, m0, m1, m2, m3, sacc);
    } else {
        hS[q * 32 + r] = pacc;
        __syncthreads();
        if (tid < 32)
            g_pool[(size_t)(b * NCH + ch) * 32 + tid] =
                hS[tid] + hS[32 + tid] + hS[64 + tid] + hS[96 + tid];
    }
}

// ---------------------------------------------------------------------------
// Kernel 4: head (pool-finish, Linear, BN(eval), GELU, Linear)
// ---------------------------------------------------------------------------
__global__ __launch_bounds__(32) void final_kernel(
        const float* __restrict__ Wh, const float* __restrict__ bh,
        const float* __restrict__ gamma, const float* __restrict__ beta,
        const float* __restrict__ mu, const float* __restrict__ var,
        const float* __restrict__ Wf, const float* __restrict__ bf,
        float* __restrict__ out) {
    int b = threadIdx.x;
    if (b >= Bn) return;
    float p[32];
#pragma unroll
    for (int c = 0; c < 32; c++) {
        float sum = 0.f;
        for (int ch = 0; ch < NCH; ch++)
            sum += g_pool[(size_t)(b * NCH + ch) * 32 + c];
        p[c] = sum * (1.0f / (float)Ln);
    }
    float z[32];
#pragma unroll
    for (int j = 0; j < 32; j++) {
        float sv = bh[j];
#pragma unroll
        for (int c = 0; c < 32; c++) sv += p[c] * Wh[c * 32 + j];
        sv = (sv - mu[j]) * rsqrtf(var[j] + 1e-5f) * gamma[j] + beta[j];
        z[j] = 0.5f * sv * (1.0f + erff(sv * 0.7071067811865476f));
    }
    for (int k = 0; k < 10; k++) {
        float sv = bf[k];
#pragma unroll
        for (int j = 0; j < 32; j++) sv += z[j] * Wf[j * 10 + k];
        out[b * 10 + k] = sv;
    }
}

// ---------------------------------------------------------------------------
extern "C" void kernel_launch(void* const* d_in, const int* in_sizes, int n_in,
                              void* d_out, int out_size) {
    const float* x    = (const float*)d_in[0];
    const float* fcW1 = (const float*)d_in[1];
    const float* fcb1 = (const float*)d_in[2];
    const float* fcW2 = (const float*)d_in[3];
    const float* fcb2 = (const float*)d_in[4];
    const float* Wh   = (const float*)d_in[5];
    const float* bh   = (const float*)d_in[6];
    const float* gam  = (const float*)d_in[7];
    const float* bet  = (const float*)d_in[8];
    const float* mu   = (const float*)d_in[9];
    const float* var  = (const float*)d_in[10];
    const float* Wf   = (const float*)d_in[11];
    const float* bf   = (const float*)d_in[12];
    float* out = (float*)d_out;

    dim3 grid(NCH, Bn);
    stats_x_kernel<<<grid, NTH>>>(x);
    combine_kernel<<<Bn, 256>>>();
    token_kernel<true,  false><<<grid, NTH>>>(x, fcW1, fcb1, fcW2, fcb2);
    combine_kernel<<<Bn, 256>>>();
    token_kernel<false, false><<<grid, NTH>>>(nullptr, fcW1 + 1024, fcb1 + 32,
                                              fcW2 + 1024, fcb2 + 32);
    combine_kernel<<<Bn, 256>>>();
    token_kernel<false, true ><<<grid, NTH>>>(nullptr, fcW1 + 2048, fcb1 + 64,
                                              fcW2 + 2048, fcb2 + 64);
    final_kernel<<<1, 32>>>(Wh, bh, gam, bet, mu, var, Wf, bf, out);
}

// round 7
// speedup vs baseline: 1.1685x; 1.0521x over previous
#include <cuda_runtime.h>
#include <math.h>
#include <stdint.h>

// ---------------------------------------------------------------------------
// CLFormer v7 for GB300 (sm_103a harness, sm_103 base ISA).
// B=32, C=32, L=16384, H=4(dh=8), NB=3.
// v7 vs v5:
//  - g_h stores eh = exp(h): attention needs zero exps, stats inner loop
//    exp-free (producer computes eh once; stages h AND eh).
//  - GELU via A&S 7.1.28 (1 rcp, no exp).
//  - combine folded into kernel epilogues via atomicAdd (+ zero kernel).
// Launches: zero, stats_x, token0, token1, token2(last), final = 6.
// ---------------------------------------------------------------------------

#define Bn 32
#define Cn 32
#define Ln 16384
#define NCH 64          // chunks per batch row
#define CHT 256         // tokens per chunk
#define NTH 128
#define NGR 2           // groups of 128 tokens per chunk
#define HST 36          // staging stride (floats), conflict-free, 16B-aligned

typedef unsigned long long u64;

__device__ float g_h[(size_t)Bn * Cn * Ln];     // 64MB: eh = exp(h) activations
__device__ float g_kvraw[3 * Bn * 288];         // per (buf,b): S[32] | M[256]
__device__ float g_pool[Bn * NCH * 32];

// ---- packed f32x2 helpers --------------------------------------------------
__device__ __forceinline__ u64 dup2(float a) {
    u64 r; asm("mov.b64 %0, {%1, %1};" : "=l"(r) : "f"(a)); return r;
}
__device__ __forceinline__ void fma2(u64& d, u64 a, u64 b) {
    asm("fma.rn.f32x2 %0, %1, %2, %0;" : "+l"(d) : "l"(a), "l"(b));
}
__device__ __forceinline__ float2 unpk(u64 v) {
    float2 f; asm("mov.b64 {%0, %1}, %2;" : "=f"(f.x), "=f"(f.y) : "l"(v)); return f;
}
__device__ __forceinline__ float frcp(float x) {
    float r; asm("rcp.approx.f32 %0, %1;" : "=f"(r) : "f"(x)); return r;
}

// GELU with A&S 7.1.28 erf (max abs err 3e-7): 1 rcp, no exp.
__device__ __forceinline__ float gelu_f(float x) {
    float z = fabsf(x) * 0.7071067811865476f;
    float u = fmaf(z, fmaf(z, fmaf(z, fmaf(z, fmaf(z, fmaf(z,
                  4.30638e-5f, 2.765672e-4f), 1.520143e-4f),
                  9.2705272e-3f), 4.22820123e-2f), 7.05230784e-2f), 1.0f);
    float t = frcp(u);
    float t2 = t * t;
    float t4 = t2 * t2;
    float t8 = t4 * t4;
    float t16 = t8 * t8;
    float er = copysignf(1.0f - t16, x);
    return 0.5f * x * (1.0f + er);
}

// ---- staging ----------------------------------------------------------------
__device__ __forceinline__ void stage_row(float* S, int tid, const float (&v)[32]) {
    float4* d = reinterpret_cast<float4*>(S + tid * HST);
#pragma unroll
    for (int k = 0; k < 8; k++)
        d[k] = make_float4(v[4 * k], v[4 * k + 1], v[4 * k + 2], v[4 * k + 3]);
}

// thread owns M row r (head=r>>3, d=r&7) over token-quarter q. No exp inside.
__device__ __forceinline__ void accum_stats(const float* hS, const float* eS,
        int r, int q, u64& m0, u64& m1, u64& m2, u64& m3, float& sacc) {
    const float* ph = hS + q * 32 * HST;
    const float* pe = eS + q * 32 * HST;
    const int eoff = (r & 24);  // head*8
#pragma unroll 4
    for (int s = 0; s < 32; s++) {
        float ed = pe[r];
        ulonglong2 hv = *reinterpret_cast<const ulonglong2*>(ph + eoff);
        ulonglong2 hw = *reinterpret_cast<const ulonglong2*>(ph + eoff + 4);
        u64 e2 = dup2(ed);
        fma2(m0, e2, hv.x); fma2(m1, e2, hv.y);
        fma2(m2, e2, hw.x); fma2(m3, e2, hw.y);
        sacc += ed;
        ph += HST; pe += HST;
    }
}

// reduce 4 quarters via smem (red aliases staging), atomicAdd into gout[288]
__device__ __forceinline__ void stats_atomic_out(float* red, float* gout, int tid,
        u64 m0, u64 m1, u64 m2, u64 m3, float sacc) {
    int r = tid & 31, q = tid >> 5;
    float2 a = unpk(m0), b = unpk(m1), c = unpk(m2), d = unpk(m3);
    float4* dst = reinterpret_cast<float4*>(red + q * 288 + r * 8);
    dst[0] = make_float4(a.x, a.y, b.x, b.y);
    dst[1] = make_float4(c.x, c.y, d.x, d.y);
    red[q * 288 + 256 + r] = sacc;
    __syncthreads();
    float M0 = red[tid] + red[288 + tid] + red[576 + tid] + red[864 + tid];
    float M1 = red[128 + tid] + red[416 + tid] + red[704 + tid] + red[992 + tid];
    atomicAdd(&gout[32 + tid], M0);
    atomicAdd(&gout[160 + tid], M1);
    if (tid < 32) {
        float S = red[256 + tid] + red[544 + tid] + red[832 + tid] + red[1120 + tid];
        atomicAdd(&gout[tid], S);
    }
}

// ---------------------------------------------------------------------------
// Kernel 0: zero the atomic accumulators (must run every graph replay)
// ---------------------------------------------------------------------------
__global__ void zero_kernel() {
    int i = blockIdx.x * 256 + threadIdx.x;
    if (i < 3 * Bn * 288) g_kvraw[i] = 0.f;
}

// ---------------------------------------------------------------------------
// Kernel 1: stats over raw x; writes eh(x) to g_h; atomics into buf 0.
// ---------------------------------------------------------------------------
__global__ __launch_bounds__(NTH) void stats_x_kernel(const float* __restrict__ x) {
    __shared__ __align__(16) float hS[NTH * HST];
    __shared__ __align__(16) float eS[NTH * HST];
    int tid = threadIdx.x, b = blockIdx.y, ch = blockIdx.x;
    int r = tid & 31, q = tid >> 5;
    const float* xb = x + (size_t)b * Cn * Ln + ch * CHT;
    float* outb = g_h + (size_t)b * Cn * Ln + ch * CHT;
    u64 m0 = 0, m1 = 0, m2 = 0, m3 = 0; float sacc = 0.f;
    for (int g = 0; g < NGR; g++) {
        int l = g * NTH + tid;
        float h[32], eh[32];
#pragma unroll
        for (int c = 0; c < 32; c++) h[c] = xb[(size_t)c * Ln + l];
#pragma unroll
        for (int c = 0; c < 32; c++) {
            eh[c] = __expf(h[c]);
            outb[(size_t)c * Ln + l] = eh[c];
        }
        stage_row(hS, tid, h);
        stage_row(eS, tid, eh);
        __syncthreads();
        accum_stats(hS, eS, r, q, m0, m1, m2, m3, sacc);
        __syncthreads();
    }
    stats_atomic_out(hS, g_kvraw + (size_t)b * 288, tid, m0, m1, m2, m3, sacc);
}

// ---------------------------------------------------------------------------
// Kernel 2: token pass. Reads eh from g_h; attention is exp-free.
// BUFIN = kv accumulator index for this block; output stats -> BUFIN+1.
// ---------------------------------------------------------------------------
template <int BUFIN, bool LAST>
__global__ __launch_bounds__(NTH) void token_kernel(
        const float* __restrict__ W1, const float* __restrict__ b1,
        const float* __restrict__ W2, const float* __restrict__ b2) {
    __shared__ __align__(16) float hS[NTH * HST];
    __shared__ __align__(16) float eS[NTH * HST];
    __shared__ __align__(16) float sW1[1024], sW2[1024], skv[256];
    __shared__ float sS[32], sb1[32], sb2[32];
    int tid = threadIdx.x, b = blockIdx.y, ch = blockIdx.x;
    int r = tid & 31, q = tid >> 5;

    // prologue: finish kv = M/S from the atomic accumulator; load weights
    const float* kvin = g_kvraw + ((size_t)BUFIN * Bn + b) * 288;
    float M0 = kvin[32 + tid], M1 = kvin[160 + tid];
    if (tid < 32) { sS[tid] = kvin[tid]; sb1[tid] = b1[tid]; sb2[tid] = b2[tid]; }
    for (int i = tid; i < 1024; i += NTH) { sW1[i] = W1[i]; sW2[i] = W2[i]; }
    __syncthreads();
    {
        int u0 = tid, u1 = tid + 128;
        int cd0 = ((u0 >> 6) << 3) | ((u0 >> 3) & 7);
        int cd1 = ((u1 >> 6) << 3) | ((u1 >> 3) & 7);
        skv[u0] = M0 / sS[cd0];
        skv[u1] = M1 / sS[cd1];
    }
    __syncthreads();

    u64 m0 = 0, m1 = 0, m2 = 0, m3 = 0; float sacc = 0.f, pacc = 0.f;
    const float* inb = g_h + (size_t)b * Cn * Ln + ch * CHT;
    float* outb = g_h + (size_t)b * Cn * Ln + ch * CHT;

    for (int g = 0; g < NGR; g++) {
        int l = g * NTH + tid;
        float eh[32];
#pragma unroll
        for (int c = 0; c < 32; c++) eh[c] = inb[(size_t)c * Ln + l];

        // ---- attention from eh: q = eh/sum; out = q @ kv (no exps) ----
        float h[32];
#pragma unroll
        for (int hd = 0; hd < 4; hd++) {
            float sum = 0.f;
#pragma unroll
            for (int d = 0; d < 8; d++) sum += eh[hd * 8 + d];
            u64 a0 = 0, a1 = 0, a2 = 0, a3 = 0;
#pragma unroll
            for (int d = 0; d < 8; d++) {
                const ulonglong2* kr = reinterpret_cast<const ulonglong2*>(&skv[hd * 64 + d * 8]);
                ulonglong2 k0 = kr[0], k1 = kr[1];
                u64 e2 = dup2(eh[hd * 8 + d]);
                fma2(a0, e2, k0.x); fma2(a1, e2, k0.y);
                fma2(a2, e2, k1.x); fma2(a3, e2, k1.y);
            }
            float inv = frcp(sum);
            float2 u;
            u = unpk(a0); h[hd * 8 + 0] = u.x * inv; h[hd * 8 + 1] = u.y * inv;
            u = unpk(a1); h[hd * 8 + 2] = u.x * inv; h[hd * 8 + 3] = u.y * inv;
            u = unpk(a2); h[hd * 8 + 4] = u.x * inv; h[hd * 8 + 5] = u.y * inv;
            u = unpk(a3); h[hd * 8 + 6] = u.x * inv; h[hd * 8 + 7] = u.y * inv;
        }

        // ---- FC1 + GELU (two j-halves) ----
        float f[32];
#pragma unroll
        for (int half = 0; half < 2; half++) {
            const int jb = half * 16;
            u64 acc[8];
            {
                const ulonglong2* bb = reinterpret_cast<const ulonglong2*>(sb1 + jb);
#pragma unroll
                for (int k = 0; k < 4; k++) { ulonglong2 v = bb[k]; acc[2 * k] = v.x; acc[2 * k + 1] = v.y; }
            }
#pragma unroll
            for (int i = 0; i < 32; i++) {
                u64 ai = dup2(h[i]);
                const ulonglong2* wr = reinterpret_cast<const ulonglong2*>(&sW1[i * 32 + jb]);
#pragma unroll
                for (int k = 0; k < 4; k++) {
                    ulonglong2 w = wr[k];
                    fma2(acc[2 * k], ai, w.x);
                    fma2(acc[2 * k + 1], ai, w.y);
                }
            }
#pragma unroll
            for (int k = 0; k < 8; k++) {
                float2 u = unpk(acc[k]);
                f[jb + 2 * k] = gelu_f(u.x);
                f[jb + 2 * k + 1] = gelu_f(u.y);
            }
        }

        // ---- FC2 + GELU (two j-halves) -> h_new ----
#pragma unroll
        for (int half = 0; half < 2; half++) {
            const int jb = half * 16;
            u64 acc[8];
            {
                const ulonglong2* bb = reinterpret_cast<const ulonglong2*>(sb2 + jb);
#pragma unroll
                for (int k = 0; k < 4; k++) { ulonglong2 v = bb[k]; acc[2 * k] = v.x; acc[2 * k + 1] = v.y; }
            }
#pragma unroll
            for (int i = 0; i < 32; i++) {
                u64 ai = dup2(f[i]);
                const ulonglong2* wr = reinterpret_cast<const ulonglong2*>(&sW2[i * 32 + jb]);
#pragma unroll
                for (int k = 0; k < 4; k++) {
                    ulonglong2 w = wr[k];
                    fma2(acc[2 * k], ai, w.x);
                    fma2(acc[2 * k + 1], ai, w.y);
                }
            }
#pragma unroll
            for (int k = 0; k < 8; k++) {
                float2 u = unpk(acc[k]);
                h[jb + 2 * k] = gelu_f(u.x);
                h[jb + 2 * k + 1] = gelu_f(u.y);
            }
        }

        if (!LAST) {
            // eh_new = exp(h_new): serves next block's attention AND our stats
            float ehn[32];
#pragma unroll
            for (int c = 0; c < 32; c++) {
                ehn[c] = __expf(h[c]);
                outb[(size_t)c * Ln + l] = ehn[c];
            }
            stage_row(hS, tid, h);
            stage_row(eS, tid, ehn);
            __syncthreads();
            accum_stats(hS, eS, r, q, m0, m1, m2, m3, sacc);
            __syncthreads();
        } else {
            stage_row(hS, tid, h);
            __syncthreads();
            const float* p = hS + q * 32 * HST;
#pragma unroll 8
            for (int s = 0; s < 32; s++) { pacc += p[r]; p += HST; }
            __syncthreads();
        }
    }

    if (!LAST) {
        stats_atomic_out(hS, g_kvraw + ((size_t)(BUFIN + 1) * Bn + b) * 288,
                         tid, m0, m1, m2, m3, sacc);
    } else {
        hS[q * 32 + r] = pacc;
        __syncthreads();
        if (tid < 32)
            g_pool[(size_t)(b * NCH + ch) * 32 + tid] =
                hS[tid] + hS[32 + tid] + hS[64 + tid] + hS[96 + tid];
    }
}

// ---------------------------------------------------------------------------
// Kernel 3: head (pool-finish, Linear, BN(eval), GELU, Linear)
// ---------------------------------------------------------------------------
__global__ __launch_bounds__(32) void final_kernel(
        const float* __restrict__ Wh, const float* __restrict__ bh,
        const float* __restrict__ gamma, const float* __restrict__ beta,
        const float* __restrict__ mu, const float* __restrict__ var,
        const float* __restrict__ Wf, const float* __restrict__ bf,
        float* __restrict__ out) {
    int b = threadIdx.x;
    if (b >= Bn) return;
    float p[32];
#pragma unroll
    for (int c = 0; c < 32; c++) {
        float sum = 0.f;
        for (int ch = 0; ch < NCH; ch++)
            sum += g_pool[(size_t)(b * NCH + ch) * 32 + c];
        p[c] = sum * (1.0f / (float)Ln);
    }
    float z[32];
#pragma unroll
    for (int j = 0; j < 32; j++) {
        float sv = bh[j];
#pragma unroll
        for (int c = 0; c < 32; c++) sv += p[c] * Wh[c * 32 + j];
        sv = (sv - mu[j]) * rsqrtf(var[j] + 1e-5f) * gamma[j] + beta[j];
        z[j] = 0.5f * sv * (1.0f + erff(sv * 0.7071067811865476f));
    }
    for (int k = 0; k < 10; k++) {
        float sv = bf[k];
#pragma unroll
        for (int j = 0; j < 32; j++) sv += z[j] * Wf[j * 10 + k];
        out[b * 10 + k] = sv;
    }
}

// ---------------------------------------------------------------------------
extern "C" void kernel_launch(void* const* d_in, const int* in_sizes, int n_in,
                              void* d_out, int out_size) {
    const float* x    = (const float*)d_in[0];
    const float* fcW1 = (const float*)d_in[1];
    const float* fcb1 = (const float*)d_in[2];
    const float* fcW2 = (const float*)d_in[3];
    const float* fcb2 = (const float*)d_in[4];
    const float* Wh   = (const float*)d_in[5];
    const float* bh   = (const float*)d_in[6];
    const float* gam  = (const float*)d_in[7];
    const float* bet  = (const float*)d_in[8];
    const float* mu   = (const float*)d_in[9];
    const float* var  = (const float*)d_in[10];
    const float* Wf   = (const float*)d_in[11];
    const float* bf   = (const float*)d_in[12];
    float* out = (float*)d_out;

    dim3 grid(NCH, Bn);
    zero_kernel<<<(3 * Bn * 288 + 255) / 256, 256>>>();
    stats_x_kernel<<<grid, NTH>>>(x);
    token_kernel<0, false><<<grid, NTH>>>(fcW1, fcb1, fcW2, fcb2);
    token_kernel<1, false><<<grid, NTH>>>(fcW1 + 1024, fcb1 + 32,
                                          fcW2 + 1024, fcb2 + 32);
    token_kernel<2, true ><<<grid, NTH>>>(fcW1 + 2048, fcb1 + 64,
                                          fcW2 + 2048, fcb2 + 64);
    final_kernel<<<1, 32>>>(Wh, bh, gam, bet, mu, var, Wf, bf, out);
}

// round 8
// speedup vs baseline: 1.1779x; 1.0080x over previous
#include <cuda_runtime.h>
#include <math.h>
#include <stdint.h>

// ---------------------------------------------------------------------------
// CLFormer v8 for GB300 (sm_103a harness, sm_103 base ISA).
// B=32, C=32, L=16384, H=4(dh=8), NB=3.
// v8 vs v7: restore __launch_bounds__(128,5) (v7 crept to 128 regs = 4 CTAs),
// drop the eS staging buffer (18KB smem) and recompute exp inline in the
// stats accumulation. Occupancy 4 -> 5 CTAs/SM.
// Launches: zero, stats_x, token0, token1, token2(last), final = 6.
// ---------------------------------------------------------------------------

#define Bn 32
#define Cn 32
#define Ln 16384
#define NCH 64          // chunks per batch row
#define CHT 256         // tokens per chunk
#define NTH 128
#define NGR 2           // groups of 128 tokens per chunk
#define HST 36          // staging stride (floats), conflict-free, 16B-aligned

typedef unsigned long long u64;

__device__ float g_h[(size_t)Bn * Cn * Ln];     // 64MB: eh = exp(h) activations
__device__ float g_kvraw[3 * Bn * 288];         // per (buf,b): S[32] | M[256]
__device__ float g_pool[Bn * NCH * 32];

// ---- packed f32x2 helpers --------------------------------------------------
__device__ __forceinline__ u64 dup2(float a) {
    u64 r; asm("mov.b64 %0, {%1, %1};" : "=l"(r) : "f"(a)); return r;
}
__device__ __forceinline__ void fma2(u64& d, u64 a, u64 b) {
    asm("fma.rn.f32x2 %0, %1, %2, %0;" : "+l"(d) : "l"(a), "l"(b));
}
__device__ __forceinline__ float2 unpk(u64 v) {
    float2 f; asm("mov.b64 {%0, %1}, %2;" : "=f"(f.x), "=f"(f.y) : "l"(v)); return f;
}
__device__ __forceinline__ float frcp(float x) {
    float r; asm("rcp.approx.f32 %0, %1;" : "=f"(r) : "f"(x)); return r;
}

// GELU with A&S 7.1.28 erf (max abs err 3e-7): 1 rcp, no exp.
__device__ __forceinline__ float gelu_f(float x) {
    float z = fabsf(x) * 0.7071067811865476f;
    float u = fmaf(z, fmaf(z, fmaf(z, fmaf(z, fmaf(z, fmaf(z,
                  4.30638e-5f, 2.765672e-4f), 1.520143e-4f),
                  9.2705272e-3f), 4.22820123e-2f), 7.05230784e-2f), 1.0f);
    float t = frcp(u);
    float t2 = t * t;
    float t4 = t2 * t2;
    float t8 = t4 * t4;
    float t16 = t8 * t8;
    float er = copysignf(1.0f - t16, x);
    return 0.5f * x * (1.0f + er);
}

// ---- staging ----------------------------------------------------------------
__device__ __forceinline__ void stage_row(float* S, int tid, const float (&v)[32]) {
    float4* d = reinterpret_cast<float4*>(S + tid * HST);
#pragma unroll
    for (int k = 0; k < 8; k++)
        d[k] = make_float4(v[4 * k], v[4 * k + 1], v[4 * k + 2], v[4 * k + 3]);
}

// thread owns M row r (head=r>>3, d=r&7) over token-quarter q; exp inline.
__device__ __forceinline__ void accum_stats(const float* hS, int r, int q,
        u64& m0, u64& m1, u64& m2, u64& m3, float& sacc) {
    const float* ph = hS + q * 32 * HST;
    const int eoff = (r & 24);  // head*8
#pragma unroll 4
    for (int s = 0; s < 32; s++) {
        float ed = __expf(ph[r]);
        ulonglong2 hv = *reinterpret_cast<const ulonglong2*>(ph + eoff);
        ulonglong2 hw = *reinterpret_cast<const ulonglong2*>(ph + eoff + 4);
        u64 e2 = dup2(ed);
        fma2(m0, e2, hv.x); fma2(m1, e2, hv.y);
        fma2(m2, e2, hw.x); fma2(m3, e2, hw.y);
        sacc += ed;
        ph += HST;
    }
}

// reduce 4 quarters via smem (red aliases staging), atomicAdd into gout[288]
__device__ __forceinline__ void stats_atomic_out(float* red, float* gout, int tid,
        u64 m0, u64 m1, u64 m2, u64 m3, float sacc) {
    int r = tid & 31, q = tid >> 5;
    float2 a = unpk(m0), b = unpk(m1), c = unpk(m2), d = unpk(m3);
    float4* dst = reinterpret_cast<float4*>(red + q * 288 + r * 8);
    dst[0] = make_float4(a.x, a.y, b.x, b.y);
    dst[1] = make_float4(c.x, c.y, d.x, d.y);
    red[q * 288 + 256 + r] = sacc;
    __syncthreads();
    float M0 = red[tid] + red[288 + tid] + red[576 + tid] + red[864 + tid];
    float M1 = red[128 + tid] + red[416 + tid] + red[704 + tid] + red[992 + tid];
    atomicAdd(&gout[32 + tid], M0);
    atomicAdd(&gout[160 + tid], M1);
    if (tid < 32) {
        float S = red[256 + tid] + red[544 + tid] + red[832 + tid] + red[1120 + tid];
        atomicAdd(&gout[tid], S);
    }
}

// ---------------------------------------------------------------------------
// Kernel 0: zero the atomic accumulators (must run every graph replay)
// ---------------------------------------------------------------------------
__global__ void zero_kernel() {
    int i = blockIdx.x * 256 + threadIdx.x;
    if (i < 3 * Bn * 288) g_kvraw[i] = 0.f;
}

// ---------------------------------------------------------------------------
// Kernel 1: stats over raw x; writes eh(x) to g_h; atomics into buf 0.
// ---------------------------------------------------------------------------
__global__ __launch_bounds__(NTH, 5) void stats_x_kernel(const float* __restrict__ x) {
    __shared__ __align__(16) float hS[NTH * HST];
    int tid = threadIdx.x, b = blockIdx.y, ch = blockIdx.x;
    int r = tid & 31, q = tid >> 5;
    const float* xb = x + (size_t)b * Cn * Ln + ch * CHT;
    float* outb = g_h + (size_t)b * Cn * Ln + ch * CHT;
    u64 m0 = 0, m1 = 0, m2 = 0, m3 = 0; float sacc = 0.f;
    for (int g = 0; g < NGR; g++) {
        int l = g * NTH + tid;
        float h[32];
#pragma unroll
        for (int c = 0; c < 32; c++) h[c] = xb[(size_t)c * Ln + l];
#pragma unroll
        for (int c = 0; c < 32; c++)
            outb[(size_t)c * Ln + l] = __expf(h[c]);
        stage_row(hS, tid, h);
        __syncthreads();
        accum_stats(hS, r, q, m0, m1, m2, m3, sacc);
        __syncthreads();
    }
    stats_atomic_out(hS, g_kvraw + (size_t)b * 288, tid, m0, m1, m2, m3, sacc);
}

// ---------------------------------------------------------------------------
// Kernel 2: token pass. Reads eh from g_h; attention is exp-free.
// BUFIN = kv accumulator index for this block; output stats -> BUFIN+1.
// ---------------------------------------------------------------------------
template <int BUFIN, bool LAST>
__global__ __launch_bounds__(NTH, 5) void token_kernel(
        const float* __restrict__ W1, const float* __restrict__ b1,
        const float* __restrict__ W2, const float* __restrict__ b2) {
    __shared__ __align__(16) float hS[NTH * HST];
    __shared__ __align__(16) float sW1[1024], sW2[1024], skv[256];
    __shared__ float sS[32], sb1[32], sb2[32];
    int tid = threadIdx.x, b = blockIdx.y, ch = blockIdx.x;
    int r = tid & 31, q = tid >> 5;

    // prologue: finish kv = M/S from the atomic accumulator; load weights
    const float* kvin = g_kvraw + ((size_t)BUFIN * Bn + b) * 288;
    float M0 = kvin[32 + tid], M1 = kvin[160 + tid];
    if (tid < 32) { sS[tid] = kvin[tid]; sb1[tid] = b1[tid]; sb2[tid] = b2[tid]; }
    for (int i = tid; i < 1024; i += NTH) { sW1[i] = W1[i]; sW2[i] = W2[i]; }
    __syncthreads();
    {
        int u0 = tid, u1 = tid + 128;
        int cd0 = ((u0 >> 6) << 3) | ((u0 >> 3) & 7);
        int cd1 = ((u1 >> 6) << 3) | ((u1 >> 3) & 7);
        skv[u0] = M0 / sS[cd0];
        skv[u1] = M1 / sS[cd1];
    }
    __syncthreads();

    u64 m0 = 0, m1 = 0, m2 = 0, m3 = 0; float sacc = 0.f, pacc = 0.f;
    const float* inb = g_h + (size_t)b * Cn * Ln + ch * CHT;
    float* outb = g_h + (size_t)b * Cn * Ln + ch * CHT;

    for (int g = 0; g < NGR; g++) {
        int l = g * NTH + tid;
        float eh[32];
#pragma unroll
        for (int c = 0; c < 32; c++) eh[c] = inb[(size_t)c * Ln + l];

        // ---- attention from eh: q = eh/sum; out = q @ kv (no exps) ----
        float h[32];
#pragma unroll
        for (int hd = 0; hd < 4; hd++) {
            float sum = 0.f;
#pragma unroll
            for (int d = 0; d < 8; d++) sum += eh[hd * 8 + d];
            u64 a0 = 0, a1 = 0, a2 = 0, a3 = 0;
#pragma unroll
            for (int d = 0; d < 8; d++) {
                const ulonglong2* kr = reinterpret_cast<const ulonglong2*>(&skv[hd * 64 + d * 8]);
                ulonglong2 k0 = kr[0], k1 = kr[1];
                u64 e2 = dup2(eh[hd * 8 + d]);
                fma2(a0, e2, k0.x); fma2(a1, e2, k0.y);
                fma2(a2, e2, k1.x); fma2(a3, e2, k1.y);
            }
            float inv = frcp(sum);
            float2 u;
            u = unpk(a0); h[hd * 8 + 0] = u.x * inv; h[hd * 8 + 1] = u.y * inv;
            u = unpk(a1); h[hd * 8 + 2] = u.x * inv; h[hd * 8 + 3] = u.y * inv;
            u = unpk(a2); h[hd * 8 + 4] = u.x * inv; h[hd * 8 + 5] = u.y * inv;
            u = unpk(a3); h[hd * 8 + 6] = u.x * inv; h[hd * 8 + 7] = u.y * inv;
        }

        // ---- FC1 + GELU (two j-halves) ----
        float f[32];
#pragma unroll
        for (int half = 0; half < 2; half++) {
            const int jb = half * 16;
            u64 acc[8];
            {
                const ulonglong2* bb = reinterpret_cast<const ulonglong2*>(sb1 + jb);
#pragma unroll
                for (int k = 0; k < 4; k++) { ulonglong2 v = bb[k]; acc[2 * k] = v.x; acc[2 * k + 1] = v.y; }
            }
#pragma unroll
            for (int i = 0; i < 32; i++) {
                u64 ai = dup2(h[i]);
                const ulonglong2* wr = reinterpret_cast<const ulonglong2*>(&sW1[i * 32 + jb]);
#pragma unroll
                for (int k = 0; k < 4; k++) {
                    ulonglong2 w = wr[k];
                    fma2(acc[2 * k], ai, w.x);
                    fma2(acc[2 * k + 1], ai, w.y);
                }
            }
#pragma unroll
            for (int k = 0; k < 8; k++) {
                float2 u = unpk(acc[k]);
                f[jb + 2 * k] = gelu_f(u.x);
                f[jb + 2 * k + 1] = gelu_f(u.y);
            }
        }

        // ---- FC2 + GELU (two j-halves) -> h_new ----
#pragma unroll
        for (int half = 0; half < 2; half++) {
            const int jb = half * 16;
            u64 acc[8];
            {
                const ulonglong2* bb = reinterpret_cast<const ulonglong2*>(sb2 + jb);
#pragma unroll
                for (int k = 0; k < 4; k++) { ulonglong2 v = bb[k]; acc[2 * k] = v.x; acc[2 * k + 1] = v.y; }
            }
#pragma unroll
            for (int i = 0; i < 32; i++) {
                u64 ai = dup2(f[i]);
                const ulonglong2* wr = reinterpret_cast<const ulonglong2*>(&sW2[i * 32 + jb]);
#pragma unroll
                for (int k = 0; k < 4; k++) {
                    ulonglong2 w = wr[k];
                    fma2(acc[2 * k], ai, w.x);
                    fma2(acc[2 * k + 1], ai, w.y);
                }
            }
#pragma unroll
            for (int k = 0; k < 8; k++) {
                float2 u = unpk(acc[k]);
                h[jb + 2 * k] = gelu_f(u.x);
                h[jb + 2 * k + 1] = gelu_f(u.y);
            }
        }

        if (!LAST) {
            // eh_new = exp(h_new) for next block's attention
#pragma unroll
            for (int c = 0; c < 32; c++)
                outb[(size_t)c * Ln + l] = __expf(h[c]);
            stage_row(hS, tid, h);
            __syncthreads();
            accum_stats(hS, r, q, m0, m1, m2, m3, sacc);
            __syncthreads();
        } else {
            stage_row(hS, tid, h);
            __syncthreads();
            const float* p = hS + q * 32 * HST;
#pragma unroll 8
            for (int s = 0; s < 32; s++) { pacc += p[r]; p += HST; }
            __syncthreads();
        }
    }

    if (!LAST) {
        stats_atomic_out(hS, g_kvraw + ((size_t)(BUFIN + 1) * Bn + b) * 288,
                         tid, m0, m1, m2, m3, sacc);
    } else {
        hS[q * 32 + r] = pacc;
        __syncthreads();
        if (tid < 32)
            g_pool[(size_t)(b * NCH + ch) * 32 + tid] =
                hS[tid] + hS[32 + tid] + hS[64 + tid] + hS[96 + tid];
    }
}

// ---------------------------------------------------------------------------
// Kernel 3: head (pool-finish, Linear, BN(eval), GELU, Linear)
// ---------------------------------------------------------------------------
__global__ __launch_bounds__(32) void final_kernel(
        const float* __restrict__ Wh, const float* __restrict__ bh,
        const float* __restrict__ gamma, const float* __restrict__ beta,
        const float* __restrict__ mu, const float* __restrict__ var,
        const float* __restrict__ Wf, const float* __restrict__ bf,
        float* __restrict__ out) {
    int b = threadIdx.x;
    if (b >= Bn) return;
    float p[32];
#pragma unroll
    for (int c = 0; c < 32; c++) {
        float sum = 0.f;
        for (int ch = 0; ch < NCH; ch++)
            sum += g_pool[(size_t)(b * NCH + ch) * 32 + c];
        p[c] = sum * (1.0f / (float)Ln);
    }
    float z[32];
#pragma unroll
    for (int j = 0; j < 32; j++) {
        float sv = bh[j];
#pragma unroll
        for (int c = 0; c < 32; c++) sv += p[c] * Wh[c * 32 + j];
        sv = (sv - mu[j]) * rsqrtf(var[j] + 1e-5f) * gamma[j] + beta[j];
        z[j] = 0.5f * sv * (1.0f + erff(sv * 0.7071067811865476f));
    }
    for (int k = 0; k < 10; k++) {
        float sv = bf[k];
#pragma unroll
        for (int j = 0; j < 32; j++) sv += z[j] * Wf[j * 10 + k];
        out[b * 10 + k] = sv;
    }
}

// ---------------------------------------------------------------------------
extern "C" void kernel_launch(void* const* d_in, const int* in_sizes, int n_in,
                              void* d_out, int out_size) {
    const float* x    = (const float*)d_in[0];
    const float* fcW1 = (const float*)d_in[1];
    const float* fcb1 = (const float*)d_in[2];
    const float* fcW2 = (const float*)d_in[3];
    const float* fcb2 = (const float*)d_in[4];
    const float* Wh   = (const float*)d_in[5];
    const float* bh   = (const float*)d_in[6];
    const float* gam  = (const float*)d_in[7];
    const float* bet  = (const float*)d_in[8];
    const float* mu   = (const float*)d_in[9];
    const float* var  = (const float*)d_in[10];
    const float* Wf   = (const float*)d_in[11];
    const float* bf   = (const float*)d_in[12];
    float* out = (float*)d_out;

    dim3 grid(NCH, Bn);
    zero_kernel<<<(3 * Bn * 288 + 255) / 256, 256>>>();
    stats_x_kernel<<<grid, NTH>>>(x);
    token_kernel<0, false><<<grid, NTH>>>(fcW1, fcb1, fcW2, fcb2);
    token_kernel<1, false><<<grid, NTH>>>(fcW1 + 1024, fcb1 + 32,
                                          fcW2 + 1024, fcb2 + 32);
    token_kernel<2, true ><<<grid, NTH>>>(fcW1 + 2048, fcb1 + 64,
                                          fcW2 + 2048, fcb2 + 64);
    final_kernel<<<1, 32>>>(Wh, bh, gam, bet, mu, var, Wf, bf, out);
}